// round 1
// baseline (speedup 1.0000x reference)
#include <cuda_runtime.h>
#include <math.h>

#define KT   100
#define VDIM 8192
#define TOPN 20

// ---------------- scratch (device globals: no allocation allowed) -----------
__device__ float  g_s[KT * VDIM];        // softmax(beta), 3.2 MB
__device__ float  g_p[KT * TOPN];        // masked-softmax probs (top-20)
__device__ int    g_idx[KT * TOPN];      // top-20 indices
__device__ int    g_colsum[VDIM];        // how many topics have v in their top-20
__device__ double g_partial[KT * 2];     // per-topic (pos, neg)

// ---------------- kernel 0: zero colsum -------------------------------------
__global__ void init_kernel() {
    int t = blockIdx.x * blockDim.x + threadIdx.x;
    if (t < VDIM) g_colsum[t] = 0;
}

// ---------------- kernel 1: per-topic softmax + top-20 ----------------------
__global__ void __launch_bounds__(256) topk_kernel(const float* __restrict__ beta) {
    __shared__ float sb[VDIM];      // 32 KB working copy of the beta row
    __shared__ float redf[256];
    __shared__ int   redi[256];
    __shared__ float topv[TOPN];
    __shared__ int   topi[TOPN];

    const int k   = blockIdx.x;
    const int tid = threadIdx.x;
    const float* brow = beta + (size_t)k * VDIM;

    for (int v = tid; v < VDIM; v += 256) sb[v] = brow[v];
    __syncthreads();

    // row max
    float m = -INFINITY;
    for (int v = tid; v < VDIM; v += 256) m = fmaxf(m, sb[v]);
    redf[tid] = m; __syncthreads();
    for (int s = 128; s > 0; s >>= 1) {
        if (tid < s) redf[tid] = fmaxf(redf[tid], redf[tid + s]);
        __syncthreads();
    }
    const float rowmax = redf[0]; __syncthreads();

    // row sum of exp
    float se = 0.f;
    for (int v = tid; v < VDIM; v += 256) se += expf(sb[v] - rowmax);
    redf[tid] = se; __syncthreads();
    for (int s = 128; s > 0; s >>= 1) {
        if (tid < s) redf[tid] += redf[tid + s];
        __syncthreads();
    }
    const float invsum = 1.0f / redf[0]; __syncthreads();

    // store full softmax(beta) row
    for (int v = tid; v < VDIM; v += 256)
        g_s[(size_t)k * VDIM + v] = expf(sb[v] - rowmax) * invsum;

    // iterative top-20 (argmax + exclusion); tie-break: lowest index (jax top_k)
    for (int it = 0; it < TOPN; ++it) {
        float bv = -INFINITY; int bi = VDIM;
        for (int v = tid; v < VDIM; v += 256) {
            float x = sb[v];
            if (x > bv) { bv = x; bi = v; }
        }
        redf[tid] = bv; redi[tid] = bi; __syncthreads();
        for (int s = 128; s > 0; s >>= 1) {
            if (tid < s) {
                float ov = redf[tid + s]; int oi = redi[tid + s];
                if (ov > redf[tid] || (ov == redf[tid] && oi < redi[tid])) {
                    redf[tid] = ov; redi[tid] = oi;
                }
            }
            __syncthreads();
        }
        if (tid == 0) {
            topv[it] = redf[0];
            topi[it] = redi[0];
            sb[redi[0]] = -INFINITY;   // exclude for the next pass
        }
        __syncthreads();
    }

    // masked softmax over the 20 survivors (max = topv[0], the global row max);
    // everything outside the top-20 underflows to exact 0 in fp32, matching ref.
    if (tid == 0) {
        const float mx = topv[0];
        float ps = 0.f;
        for (int j = 0; j < TOPN; ++j) ps += expf(topv[j] - mx);
        const float invp = 1.0f / ps;
        for (int j = 0; j < TOPN; ++j) {
            g_p[k * TOPN + j]   = expf(topv[j] - mx) * invp;
            g_idx[k * TOPN + j] = topi[j];
            atomicAdd(&g_colsum[topi[j]], 1);
        }
    }
}

// ---------------- kernel 2: sparse p@W, min-max, loss, pos/neg --------------
__global__ void __launch_bounds__(1024) loss_kernel(const float* __restrict__ Wmat) {
    __shared__ float sp[TOPN];
    __shared__ int   si[TOPN];
    __shared__ float red1[1024];
    __shared__ float red2[1024];

    const int k   = blockIdx.x;
    const int tid = threadIdx.x;

    if (tid < TOPN) {
        sp[tid] = g_p[k * TOPN + tid];
        si[tid] = g_idx[k * TOPN + tid];
    }
    __syncthreads();

    // M[k, v] = sum_j p_j * W[idx_j, v]   (8 columns per thread)
    float acc[8];
    #pragma unroll
    for (int c = 0; c < 8; ++c) acc[c] = 0.f;

    #pragma unroll
    for (int j = 0; j < TOPN; ++j) {
        const float pj = sp[j];
        const float* __restrict__ row = Wmat + (size_t)si[j] * VDIM;
        #pragma unroll
        for (int c = 0; c < 8; ++c)
            acc[c] = fmaf(pj, __ldg(row + tid + c * 1024), acc[c]);
    }

    // block min/max over M row
    float mn = acc[0], mx = acc[0];
    #pragma unroll
    for (int c = 1; c < 8; ++c) { mn = fminf(mn, acc[c]); mx = fmaxf(mx, acc[c]); }
    red1[tid] = mn; red2[tid] = mx; __syncthreads();
    for (int s = 512; s > 0; s >>= 1) {
        if (tid < s) {
            red1[tid] = fminf(red1[tid], red1[tid + s]);
            red2[tid] = fmaxf(red2[tid], red2[tid + s]);
        }
        __syncthreads();
    }
    mn = red1[0]; mx = red2[0]; __syncthreads();
    const float invr = 1.0f / (mx - mn);

    // loss + diversity split
    float pos = 0.f, neg = 0.f;
    #pragma unroll
    for (int c = 0; c < 8; ++c) {
        const int v   = tid + c * 1024;
        const float wc = 1.0f - (acc[c] - mn) * invr;
        const float sv = g_s[(size_t)k * VDIM + v];
        const float l  = 100.0f * sv * sv * wc;
        const int cs   = g_colsum[v];
        int inmask = 0;
        #pragma unroll
        for (int j = 0; j < TOPN; ++j) inmask |= (si[j] == v);
        if (cs - inmask > 0) pos += l; else neg += l;
    }
    red1[tid] = pos; red2[tid] = neg; __syncthreads();
    for (int s = 512; s > 0; s >>= 1) {
        if (tid < s) { red1[tid] += red1[tid + s]; red2[tid] += red2[tid + s]; }
        __syncthreads();
    }
    if (tid == 0) {
        g_partial[2 * k]     = (double)red1[0];
        g_partial[2 * k + 1] = (double)red2[0];
    }
}

// ---------------- kernel 3: reduce partials, apply lambdas ------------------
__global__ void final_kernel(const int* __restrict__ epoch, float* __restrict__ out) {
    double pos = 0.0, neg = 0.0;
    for (int k = 0; k < KT; ++k) {
        pos += g_partial[2 * k];
        neg += g_partial[2 * k + 1];
    }
    const int e = *epoch;                       // warmup_epochs = 100
    const float lam = (e < 100) ? (float)e : 100.0f;   // lambda_a_delta = 1.0
    const float total = (float)((pos * 0.7 + neg * 0.3) * 2.0);
    out[0] = lam * total;
}

// ---------------- launch -----------------------------------------------------
extern "C" void kernel_launch(void* const* d_in, const int* in_sizes, int n_in,
                              void* d_out, int out_size) {
    const float* beta  = (const float*)d_in[0];
    const float* Wmat  = (const float*)d_in[1];
    const int*   epoch = (const int*)d_in[2];
    float* out = (float*)d_out;

    init_kernel<<<(VDIM + 255) / 256, 256>>>();
    topk_kernel<<<KT, 256>>>(beta);
    loss_kernel<<<KT, 1024>>>(Wmat);
    final_kernel<<<1, 1>>>(epoch, out);
}

// round 2
// speedup vs baseline: 1.6638x; 1.6638x over previous
#include <cuda_runtime.h>
#include <math.h>

#define KT     100
#define VDIM   8192
#define TOPN   20
#define NWORDS (VDIM / 32)   // 256 bitmask words

// ---------------- scratch (device globals; zero-initialized at load) --------
__device__ float    g_p[KT * TOPN];      // masked-softmax probs
__device__ int      g_idx[KT * TOPN];    // top-20 indices
__device__ float2   g_stat[KT];          // (rowmax, invsum) of softmax(beta)
__device__ unsigned g_U1[NWORDS];        // bit v: v in >=1 topic's top-20
__device__ unsigned g_U2[NWORDS];        // bit v: v in >=2 topics' top-20
__device__ double   g_partial[KT * 2];   // per-topic (pos, neg)
__device__ unsigned g_done;              // completion counter

// ============ kernel 1: softmax stats + top-20 + union bitmasks =============
__global__ void __launch_bounds__(256) topk_kernel(const float* __restrict__ beta) {
    __shared__ float sb[VDIM];           // 32 KB row copy
    __shared__ float wred[8];
    __shared__ float candv[8 * TOPN];
    __shared__ int   candi[8 * TOPN];
    __shared__ float topv[TOPN];
    __shared__ int   topi[TOPN];

    const int k    = blockIdx.x;
    const int tid  = threadIdx.x;
    const int warp = tid >> 5;
    const int lane = tid & 31;

    // coalesced float4 load of the beta row into smem
    const float4* b4 = (const float4*)(beta + (size_t)k * VDIM);
    float4* s4 = (float4*)sb;
    for (int i = tid; i < VDIM / 4; i += 256) s4[i] = b4[i];
    __syncthreads();

    // ---- row max (warp shuffle + 8-word smem) ----
    float m = -INFINITY;
    for (int v = tid; v < VDIM; v += 256) m = fmaxf(m, sb[v]);
    #pragma unroll
    for (int o = 16; o; o >>= 1) m = fmaxf(m, __shfl_xor_sync(0xFFFFFFFFu, m, o));
    if (lane == 0) wred[warp] = m;
    __syncthreads();
    if (warp == 0) {
        m = wred[lane & 7];
        #pragma unroll
        for (int o = 4; o; o >>= 1) m = fmaxf(m, __shfl_xor_sync(0xFFFFFFFFu, m, o));
        if (lane == 0) wred[0] = m;
    }
    __syncthreads();
    const float rowmax = wred[0];
    __syncthreads();

    // ---- sum of exp ----
    float se = 0.f;
    for (int v = tid; v < VDIM; v += 256) se += expf(sb[v] - rowmax);
    #pragma unroll
    for (int o = 16; o; o >>= 1) se += __shfl_xor_sync(0xFFFFFFFFu, se, o);
    if (lane == 0) wred[warp] = se;
    __syncthreads();
    if (warp == 0) {
        se = wred[lane & 7];
        #pragma unroll
        for (int o = 4; o; o >>= 1) se += __shfl_xor_sync(0xFFFFFFFFu, se, o);
        if (lane == 0) wred[0] = se;
    }
    __syncthreads();
    const float invsum = 1.0f / wred[0];
    if (tid == 0) g_stat[k] = make_float2(rowmax, invsum);

    // ---- per-warp top-20 over its 1024-element segment (cached argmax) ----
    const int base = warp * 1024;
    float bv = -INFINITY; int bi = 0x7fffffff;
    #pragma unroll
    for (int i = 0; i < 32; ++i) {           // ascending v per lane -> strict >
        int v = base + i * 32 + lane;        //   keeps lowest index on ties
        float x = sb[v];
        if (x > bv) { bv = x; bi = v; }
    }
    for (int it = 0; it < TOPN; ++it) {
        float rv = bv; int ri = bi;
        #pragma unroll
        for (int o = 16; o; o >>= 1) {
            float ov = __shfl_xor_sync(0xFFFFFFFFu, rv, o);
            int   oi = __shfl_xor_sync(0xFFFFFFFFu, ri, o);
            if (ov > rv || (ov == rv && oi < ri)) { rv = ov; ri = oi; }
        }
        if (lane == 0) { candv[warp * TOPN + it] = rv; candi[warp * TOPN + it] = ri; }
        // owner lane removes the winner and rescans its 32 elements
        if ((ri & 31) == lane) {
            sb[ri] = -INFINITY;
            bv = -INFINITY; bi = 0x7fffffff;
            #pragma unroll
            for (int i = 0; i < 32; ++i) {
                int v = base + i * 32 + lane;
                float x = sb[v];
                if (x > bv) { bv = x; bi = v; }
            }
        }
        __syncwarp();
    }
    __syncthreads();

    // ---- warp 0 merges 160 candidates -> global top-20 ----
    if (warp == 0) {
        for (int it = 0; it < TOPN; ++it) {
            float mv = -INFINITY; int mi = 0x7fffffff; int ms = -1;
            #pragma unroll
            for (int i = 0; i < 5; ++i) {
                int c = lane + i * 32;
                float x = candv[c]; int ix = candi[c];
                if (x > mv || (x == mv && ix < mi)) { mv = x; mi = ix; ms = c; }
            }
            #pragma unroll
            for (int o = 16; o; o >>= 1) {
                float ov = __shfl_xor_sync(0xFFFFFFFFu, mv, o);
                int   oi = __shfl_xor_sync(0xFFFFFFFFu, mi, o);
                int   os = __shfl_xor_sync(0xFFFFFFFFu, ms, o);
                if (ov > mv || (ov == mv && oi < mi)) { mv = ov; mi = oi; ms = os; }
            }
            if (lane == 0) { topv[it] = mv; topi[it] = mi; candv[ms] = -INFINITY; }
            __syncwarp();
        }

        // masked softmax over the 20 survivors (non-top entries underflow to
        // exact 0 in fp32 in the reference, so this is exact)
        float e = (lane < TOPN) ? expf(topv[lane] - rowmax) : 0.f;
        float s = e;
        #pragma unroll
        for (int o = 16; o; o >>= 1) s += __shfl_xor_sync(0xFFFFFFFFu, s, o);
        const float invp = 1.0f / s;

        if (lane < TOPN) {
            g_p[k * TOPN + lane]   = e * invp;
            int ix = topi[lane];
            g_idx[k * TOPN + lane] = ix;
            unsigned w = (unsigned)ix >> 5, mb = 1u << (ix & 31);
            unsigned old = atomicOr(&g_U1[w], mb);
            if (old & mb) atomicOr(&g_U2[w], mb);   // second (or later) setter
        }
    }
}

// ===== kernel 2: sparse p@W, min-max, loss, pos/neg + fused final sum =======
__global__ void __launch_bounds__(1024) loss_kernel(
    const float* __restrict__ Wmat, const float* __restrict__ beta,
    const int* __restrict__ epoch, float* __restrict__ out)
{
    __shared__ float    sp[TOPN];
    __shared__ int      si[TOPN];
    __shared__ unsigned sown[NWORDS];
    __shared__ float    r1[32], r2[32];
    __shared__ double   d1[32], d2[32];
    __shared__ float2   stat_s;
    __shared__ int      is_last;

    const int k    = blockIdx.x;
    const int tid  = threadIdx.x;
    const int warp = tid >> 5;
    const int lane = tid & 31;

    if (tid < NWORDS) sown[tid] = 0u;
    if (tid < TOPN) { sp[tid] = g_p[k * TOPN + tid]; si[tid] = g_idx[k * TOPN + tid]; }
    if (tid == 0) stat_s = g_stat[k];
    __syncthreads();
    if (tid < TOPN) { int ix = si[tid]; atomicOr(&sown[ix >> 5], 1u << (ix & 31)); }
    __syncthreads();

    // ---- M[k, v0..v0+7] = sum_j p_j * W[idx_j, v0..v0+7]  (float4 x2) ----
    const int v0 = tid * 8;
    float acc[8];
    #pragma unroll
    for (int c = 0; c < 8; ++c) acc[c] = 0.f;
    #pragma unroll
    for (int j = 0; j < TOPN; ++j) {
        const float pj = sp[j];
        const float4* r4 = (const float4*)(Wmat + (size_t)si[j] * VDIM + v0);
        float4 a = __ldg(r4);
        float4 b = __ldg(r4 + 1);
        acc[0] = fmaf(pj, a.x, acc[0]); acc[1] = fmaf(pj, a.y, acc[1]);
        acc[2] = fmaf(pj, a.z, acc[2]); acc[3] = fmaf(pj, a.w, acc[3]);
        acc[4] = fmaf(pj, b.x, acc[4]); acc[5] = fmaf(pj, b.y, acc[5]);
        acc[6] = fmaf(pj, b.z, acc[6]); acc[7] = fmaf(pj, b.w, acc[7]);
    }

    // ---- block min/max (shuffle + 32-word smem; 2 barriers) ----
    float mn = acc[0], mx = acc[0];
    #pragma unroll
    for (int c = 1; c < 8; ++c) { mn = fminf(mn, acc[c]); mx = fmaxf(mx, acc[c]); }
    #pragma unroll
    for (int o = 16; o; o >>= 1) {
        mn = fminf(mn, __shfl_xor_sync(0xFFFFFFFFu, mn, o));
        mx = fmaxf(mx, __shfl_xor_sync(0xFFFFFFFFu, mx, o));
    }
    if (lane == 0) { r1[warp] = mn; r2[warp] = mx; }
    __syncthreads();
    if (warp == 0) {
        mn = r1[lane]; mx = r2[lane];
        #pragma unroll
        for (int o = 16; o; o >>= 1) {
            mn = fminf(mn, __shfl_xor_sync(0xFFFFFFFFu, mn, o));
            mx = fmaxf(mx, __shfl_xor_sync(0xFFFFFFFFu, mx, o));
        }
        if (lane == 0) { r1[0] = mn; r2[0] = mx; }
    }
    __syncthreads();
    mn = r1[0]; mx = r2[0];
    const float invr = 1.0f / (mx - mn);

    // ---- loss + diversity split (softmax recomputed from beta + stats) ----
    const float4* be4 = (const float4*)(beta + (size_t)k * VDIM + v0);
    float4 ba = __ldg(be4), bb = __ldg(be4 + 1);
    float bv[8] = {ba.x, ba.y, ba.z, ba.w, bb.x, bb.y, bb.z, bb.w};

    const unsigned word = (unsigned)v0 >> 5;
    const unsigned u1 = g_U1[word], u2 = g_U2[word], ow = sown[word];
    const int shift = v0 & 31;
    const float rmax = stat_s.x, isum = stat_s.y;

    float pos = 0.f, neg = 0.f;
    #pragma unroll
    for (int c = 0; c < 8; ++c) {
        const float wc = 1.0f - (acc[c] - mn) * invr;
        const float sv = expf(bv[c] - rmax) * isum;
        const float l  = 100.0f * sv * sv * wc;
        const unsigned mb = 1u << (shift + c);
        const bool md = (ow & mb) ? (u2 & mb) : (u1 & mb);
        if (md) pos += l; else neg += l;
    }
    __syncthreads();   // r1/r2 reuse
    #pragma unroll
    for (int o = 16; o; o >>= 1) {
        pos += __shfl_xor_sync(0xFFFFFFFFu, pos, o);
        neg += __shfl_xor_sync(0xFFFFFFFFu, neg, o);
    }
    if (lane == 0) { r1[warp] = pos; r2[warp] = neg; }
    __syncthreads();
    if (warp == 0) {
        pos = r1[lane]; neg = r2[lane];
        #pragma unroll
        for (int o = 16; o; o >>= 1) {
            pos += __shfl_xor_sync(0xFFFFFFFFu, pos, o);
            neg += __shfl_xor_sync(0xFFFFFFFFu, neg, o);
        }
    }

    // ---- publish partial; last block finishes the job ----
    if (tid == 0) {
        g_partial[2 * k]     = (double)pos;
        g_partial[2 * k + 1] = (double)neg;
        __threadfence();
        unsigned r = atomicAdd(&g_done, 1u);
        is_last = (r == KT - 1);
    }
    __syncthreads();

    if (is_last) {
        __threadfence();
        double p = (tid < KT) ? g_partial[2 * tid]     : 0.0;
        double n = (tid < KT) ? g_partial[2 * tid + 1] : 0.0;
        #pragma unroll
        for (int o = 16; o; o >>= 1) {
            p += __shfl_xor_sync(0xFFFFFFFFu, p, o);
            n += __shfl_xor_sync(0xFFFFFFFFu, n, o);
        }
        if (lane == 0) { d1[warp] = p; d2[warp] = n; }
        __syncthreads();
        if (warp == 0) {
            p = d1[lane]; n = d2[lane];
            #pragma unroll
            for (int o = 16; o; o >>= 1) {
                p += __shfl_xor_sync(0xFFFFFFFFu, p, o);
                n += __shfl_xor_sync(0xFFFFFFFFu, n, o);
            }
            if (lane == 0) {
                const int e = *epoch;                        // warmup = 100, delta = 1.0
                const float lam = (e < 100) ? (float)e : 100.0f;
                out[0] = lam * (float)((p * 0.7 + n * 0.3) * 2.0);
                g_done = 0;                                  // reset for next replay
            }
        }
        // reset union bitmasks for the next replay (all readers are done)
        if (tid < NWORDS) { g_U1[tid] = 0u; g_U2[tid] = 0u; }
    }
}

// ---------------- launch -----------------------------------------------------
extern "C" void kernel_launch(void* const* d_in, const int* in_sizes, int n_in,
                              void* d_out, int out_size) {
    const float* beta  = (const float*)d_in[0];
    const float* Wmat  = (const float*)d_in[1];
    const int*   epoch = (const int*)d_in[2];
    float* out = (float*)d_out;

    topk_kernel<<<KT, 256>>>(beta);
    loss_kernel<<<KT, 1024>>>(Wmat, beta, epoch, out);
}